// round 15
// baseline (speedup 1.0000x reference)
#include <cuda_runtime.h>
#include <cuda_fp16.h>
#include <cstdint>
#include <math.h>

#define B_ 4
#define T_ 2048
#define C_ 1024
#define H_ 16
#define D_ 64

// Scratch (__device__ globals; allocation-free rule)
__device__ __half g_qkvh[(size_t)B_ * T_ * 3 * C_];   // [B*T, 3C] fp16
__device__ __half g_attnh[(size_t)B_ * T_ * C_];      // [B*T, C] fp16
__device__ __half g_xh[(size_t)B_ * T_ * C_];         // fp16 x
__device__ __half g_wqkvh[(size_t)3 * C_ * C_];       // fp16 w_qkv
__device__ __half g_wouth[(size_t)C_ * C_];           // fp16 w_out

// ---------------------------------------------------------------------------
__device__ __forceinline__ uint32_t smem_u32(const void* p) {
    uint32_t a;
    asm("{ .reg .u64 t; cvta.to.shared.u64 t, %1; cvt.u32.u64 %0, t; }" : "=r"(a) : "l"(p));
    return a;
}

__device__ __forceinline__ void cp_async16(uint32_t s, const void* g) {
    asm volatile("cp.async.cg.shared.global [%0], [%1], 16;" :: "r"(s), "l"(g));
}

__device__ __forceinline__ void mma_f16(float c[4], uint32_t a0, uint32_t a1,
                                        uint32_t a2, uint32_t a3,
                                        uint32_t b0, uint32_t b1)
{
    asm volatile(
        "mma.sync.aligned.m16n8k16.row.col.f32.f16.f16.f32 "
        "{%0,%1,%2,%3}, {%4,%5,%6,%7}, {%8,%9}, {%0,%1,%2,%3};"
        : "+f"(c[0]), "+f"(c[1]), "+f"(c[2]), "+f"(c[3])
        : "r"(a0), "r"(a1), "r"(a2), "r"(a3), "r"(b0), "r"(b1));
}

__device__ __forceinline__ void ldmx4(uint32_t& r0, uint32_t& r1, uint32_t& r2,
                                      uint32_t& r3, uint32_t a)
{
    asm volatile("ldmatrix.sync.aligned.m8n8.x4.shared.b16 {%0,%1,%2,%3}, [%4];"
                 : "=r"(r0), "=r"(r1), "=r"(r2), "=r"(r3) : "r"(a));
}

__device__ __forceinline__ void ldmx4t(uint32_t& r0, uint32_t& r1, uint32_t& r2,
                                       uint32_t& r3, uint32_t a)
{
    asm volatile("ldmatrix.sync.aligned.m8n8.x4.trans.shared.b16 {%0,%1,%2,%3}, [%4];"
                 : "=r"(r0), "=r"(r1), "=r"(r2), "=r"(r3) : "r"(a));
}

__device__ __forceinline__ uint32_t pack_h2(float lo, float hi) {
    __half2 h = __floats2half2_rn(lo, hi);
    return *(uint32_t*)&h;
}

// ---- mbarrier helpers -----------------------------------------------------
__device__ __forceinline__ void mbar_init(uint32_t bar, uint32_t cnt) {
    asm volatile("mbarrier.init.shared.b64 [%0], %1;" :: "r"(bar), "r"(cnt) : "memory");
}
__device__ __forceinline__ void mbar_arrive(uint32_t bar) {
    asm volatile("mbarrier.arrive.shared.b64 _, [%0];" :: "r"(bar) : "memory");
}
__device__ __forceinline__ void cp_arrive_noinc(uint32_t bar) {
    asm volatile("cp.async.mbarrier.arrive.noinc.shared.b64 [%0];" :: "r"(bar) : "memory");
}
__device__ __forceinline__ void mbar_wait(uint32_t bar, uint32_t parity) {
    uint32_t done;
    asm volatile(
        "{\n\t.reg .pred p;\n\t"
        "mbarrier.try_wait.parity.acquire.cta.shared::cta.b64 p, [%1], %2;\n\t"
        "selp.b32 %0, 1, 0, p;\n\t}"
        : "=r"(done) : "r"(bar), "r"(parity) : "memory");
    if (!done) {
        asm volatile(
            "{\n\t.reg .pred P1;\n\t"
            "WL_%=:\n\t"
            "mbarrier.try_wait.parity.acquire.cta.shared::cta.b64 P1, [%0], %1, 0x989680;\n\t"
            "@P1 bra.uni WD_%=;\n\t"
            "bra.uni WL_%=;\n\t"
            "WD_%=:\n\t}"
            :: "r"(bar), "r"(parity) : "memory");
    }
}

// ---------------------------------------------------------------------------
// fused fp32 -> fp16 (RTN) convert for x, w_qkv, w_out in ONE launch
// ---------------------------------------------------------------------------
#define N8_X  ((B_ * T_ * C_) / 8)
#define N8_WQ ((3 * C_ * C_) / 8)
#define N8_WO ((C_ * C_) / 8)
#define N8_TOT (N8_X + N8_WQ + N8_WO)

__device__ __forceinline__ void cvt8(const float4* in, uint4* out, int i) {
    float4 a = in[2 * i], b = in[2 * i + 1];
    uint4 o;
    o.x = pack_h2(a.x, a.y); o.y = pack_h2(a.z, a.w);
    o.z = pack_h2(b.x, b.y); o.w = pack_h2(b.z, b.w);
    out[i] = o;
}

__global__ __launch_bounds__(256) void convert_all_kernel(
    const float4* __restrict__ x, uint4* __restrict__ xh,
    const float4* __restrict__ wq, uint4* __restrict__ wqh,
    const float4* __restrict__ wo, uint4* __restrict__ woh)
{
    int i = blockIdx.x * blockDim.x + threadIdx.x;
    if (i < N8_X) cvt8(x, xh, i);
    else if (i < N8_X + N8_WQ) cvt8(wq, wqh, i - N8_X);
    else if (i < N8_TOT) cvt8(wo, woh, i - N8_X - N8_WQ);
}

// ---------------------------------------------------------------------------
// fp16 mma.sync GEMM (128x128, BK=64, 3-stage, 2 CTAs/SM), K=1024 hardcoded.
// MBARRIER producer/consumer pipeline: no __syncthreads in the main loop —
// warps skew freely across stages (full: 256 cp-arrivals; empty: 8 warp-arrivals).
// ---------------------------------------------------------------------------
#define G_K 1024
#define G_BM 128
#define G_BN 128
#define G_BK 64
#define G_NK (G_K / G_BK)                          // 16
#define G_ST 3
#define G_LDH 72
#define STAGE_H ((G_BM + G_BN) * G_LDH)            // 18432 halves
#define G_SMEM (1024 + G_ST * STAGE_H * 2)         // 111616 B

__global__ __launch_bounds__(256, 2) void gemm_mma_f16(
    const __half* __restrict__ A, const __half* __restrict__ Bw,
    const float* __restrict__ bias, float* __restrict__ Cf,
    __half* __restrict__ Ch, int N)
{
    extern __shared__ __half smh[];
    const int tid = threadIdx.x;
    const int lane = tid & 31, wid = tid >> 5;
    const int warp_m = (wid >> 2) * 64;
    const int warp_n = (wid & 3) * 32;
    const int bm = blockIdx.y * G_BM;
    const int bn = blockIdx.x * G_BN;
    const int lm = lane >> 2, lk = lane & 3;
    const int g = lane >> 3, li = lane & 7;

    uint32_t smbase = smem_u32(smh);         // barriers live here
    const uint32_t stg = smbase + 1024;      // stage data base
    // barriers: full[s] at smbase + 8s; empty[s] at smbase + 24 + 8s
    if (tid == 0) {
#pragma unroll
        for (int s = 0; s < G_ST; s++) {
            mbar_init(smbase + 8 * s, 256);
            mbar_init(smbase + 24 + 8 * s, 8);
        }
    }
    __syncthreads();

    float c[4][4][4];
#pragma unroll
    for (int mf = 0; mf < 4; mf++)
#pragma unroll
        for (int nf = 0; nf < 4; nf++)
#pragma unroll
            for (int r = 0; r < 4; r++) c[mf][nf][r] = 0.f;

    const int crow = tid >> 3, cseg = tid & 7;
    const __half* aBase = A + (size_t)(bm + crow) * G_K + cseg * 8;
    const __half* bBase = Bw + (size_t)(bn + crow) * G_K + cseg * 8;
    const uint32_t dstoff = (uint32_t)((crow * G_LDH + cseg * 8) * 2);

    const uint32_t fa = (uint32_t)(((warp_m + ((g & 1) << 3) + li) * G_LDH + ((g >> 1) << 3)) * 2);
    const uint32_t fb = (uint32_t)(((128 + warp_n + ((g & 1) << 3) + li) * G_LDH + ((g >> 1) << 3)) * 2);

    auto issue_stage = [&](int chunk, int s) {
        uint32_t st = stg + (uint32_t)(s * STAGE_H) * 2 + dstoff;
        const __half* Ag = aBase + chunk * G_BK;
        const __half* Bg = bBase + chunk * G_BK;
#pragma unroll
        for (int it = 0; it < 4; it++)
            cp_async16(st + (uint32_t)(it * 32 * G_LDH * 2), Ag + it * 32 * G_K);
#pragma unroll
        for (int it = 0; it < 4; it++)
            cp_async16(st + (uint32_t)((128 + it * 32) * G_LDH * 2), Bg + it * 32 * G_K);
        cp_arrive_noinc(smbase + 8 * s);
    };

    // prologue: chunks 0,1 into stages 0,1 (no empty-wait needed)
    issue_stage(0, 0);
    issue_stage(1, 1);

    int fph0 = 0, fph1 = 0, fph2 = 0;    // full-phase per stage
    int eph0 = 0, eph1 = 0, eph2 = 0;    // empty-phase per stage

    for (int i = 0; i < G_NK; i++) {
        const int s = i % G_ST;
        // wait data for chunk i
        {
            int* fp = (s == 0) ? &fph0 : (s == 1) ? &fph1 : &fph2;
            mbar_wait(smbase + 8 * s, *fp);
            *fp ^= 1;
        }

        const int j = i + G_ST - 1;
        const bool doLoad = (j < G_NK);
        const int s2 = j % G_ST;
        if (doLoad && j >= G_ST) {        // stage s2 last consumed at iter i-1
            int* ep = (s2 == 0) ? &eph0 : (s2 == 1) ? &eph1 : &eph2;
            mbar_wait(smbase + 24 + 8 * s2, *ep);
            *ep ^= 1;
        }

        const uint32_t ldst = stg + (uint32_t)(s2 * STAGE_H) * 2 + dstoff;
        const __half* Ag = aBase + j * G_BK;
        const __half* Bg = bBase + j * G_BK;

        const uint32_t st = stg + (uint32_t)(s * STAGE_H) * 2;
#pragma unroll
        for (int ks = 0; ks < 4; ks++) {
            if (doLoad) {   // spread next-stage loads: 2 per ks
                cp_async16(ldst + (uint32_t)(ks * 32 * G_LDH * 2), Ag + ks * 32 * G_K);
                cp_async16(ldst + (uint32_t)((128 + ks * 32) * G_LDH * 2), Bg + ks * 32 * G_K);
            }
            uint32_t a[4][4], b0[2], b1[2], b2[2], b3[2];
#pragma unroll
            for (int mf = 0; mf < 4; mf++)
                ldmx4(a[mf][0], a[mf][1], a[mf][2], a[mf][3],
                      st + fa + (uint32_t)((mf * 16 * G_LDH + ks * 16) * 2));
#pragma unroll
            for (int p = 0; p < 2; p++)
                ldmx4(b0[p], b1[p], b2[p], b3[p],
                      st + fb + (uint32_t)((p * 16 * G_LDH + ks * 16) * 2));
#pragma unroll
            for (int mf = 0; mf < 4; mf++)
#pragma unroll
                for (int p = 0; p < 2; p++) {
                    mma_f16(c[mf][2 * p], a[mf][0], a[mf][1], a[mf][2], a[mf][3],
                            b0[p], b2[p]);
                    mma_f16(c[mf][2 * p + 1], a[mf][0], a[mf][1], a[mf][2], a[mf][3],
                            b1[p], b3[p]);
                }
        }
        if (doLoad) cp_arrive_noinc(smbase + 8 * s2);

        __syncwarp();
        if (lane == 0) mbar_arrive(smbase + 24 + 8 * s);   // this warp done with stage s
    }

#pragma unroll
    for (int mf = 0; mf < 4; mf++) {
        int m = bm + warp_m + mf * 16 + lm;
#pragma unroll
        for (int nf = 0; nf < 4; nf++) {
            int n = bn + warp_n + nf * 8 + 2 * lk;
            if (Ch) {
                *(uint32_t*)(Ch + (size_t)m * N + n) = pack_h2(c[mf][nf][0], c[mf][nf][1]);
                *(uint32_t*)(Ch + (size_t)(m + 8) * N + n) = pack_h2(c[mf][nf][2], c[mf][nf][3]);
            } else {
                float bx = bias ? bias[n] : 0.f, by = bias ? bias[n + 1] : 0.f;
                *(float2*)(Cf + (size_t)m * N + n) =
                    make_float2(c[mf][nf][0] + bx, c[mf][nf][1] + by);
                *(float2*)(Cf + (size_t)(m + 8) * N + n) =
                    make_float2(c[mf][nf][2] + bx, c[mf][nf][3] + by);
            }
        }
    }
}

// ---------------------------------------------------------------------------
// Flash attention (BM=128, BN=64, 8 warps, 2 CTAs/SM), mbarrier pipeline.
// Q frags in regs; K,V 3-stage cp.async; V via ldmatrix.trans; P in regs.
// No __syncthreads in kv loop; masked-group skip in last two iterations.
// ---------------------------------------------------------------------------
#define FBM 128
#define FBN 64
#define FLDH 72
#define KSTG (64 * FLDH)
#define QOFF_B (1024 + 6 * KSTG * 2)           // byte offset of Q after bars+stages
#define FSM_BYTES (QOFF_B + 128 * FLDH * 2)    // 74752 B

__global__ __launch_bounds__(256, 2) void flash_mma_f16(
    const __half* __restrict__ qkv, __half* __restrict__ out)
{
    extern __shared__ __half smh[];
    const int tid = threadIdx.x, lane = tid & 31, wid = tid >> 5;
    const int lm = lane >> 2, lk = lane & 3;
    const int g = lane >> 3, li = lane & 7;
    const int warp_m = wid * 16;
    const int qtile = gridDim.x - 1 - blockIdx.x;    // heavy tiles first
    const int q0 = qtile * FBM;
    const int bh = blockIdx.y;
    const int b = bh >> 4, h = bh & 15;
    const size_t rs = 3 * C_;

    const __half* qptr = qkv + (size_t)(b * T_ + q0) * rs + h * D_;

    uint32_t smb = smem_u32(smh);          // barriers at smb
    const uint32_t stg = smb + 1024;       // K stages [0,3), V stages [3,6)
    const int nit = q0 / FBN + 2;

    if (tid == 0) {
#pragma unroll
        for (int s = 0; s < 3; s++) {
            mbar_init(smb + 8 * s, 256);        // full
            mbar_init(smb + 24 + 8 * s, 8);     // empty
        }
    }
    __syncthreads();

    const int crow = tid >> 3, cseg = tid & 7;
    const __half* kBase = qkv + (size_t)(b * T_ + crow) * rs + C_ + h * D_ + cseg * 8;
    const __half* vBase = kBase + C_;
    const uint32_t kdst = (uint32_t)((crow * FLDH + cseg * 8) * 2);

    const uint32_t fkb = (uint32_t)(((((g & 1) << 3) + li) * FLDH + ((g >> 1) << 3)) * 2);
    const uint32_t fvb = (uint32_t)(((((g >> 1) << 3) + li) * FLDH + ((g & 1) << 3)) * 2);
    const uint32_t fqb = (uint32_t)QOFF_B +
        (uint32_t)(((warp_m + ((g & 1) << 3) + li) * FLDH + ((g >> 1) << 3)) * 2);

    auto load_kv = [&](int it, int s) {
        const __half* kg = kBase + (size_t)(it * FBN) * rs;
        const __half* vg = vBase + (size_t)(it * FBN) * rs;
        uint32_t kd = stg + (uint32_t)(s * KSTG) * 2 + kdst;
        uint32_t vd = stg + (uint32_t)((3 + s) * KSTG) * 2 + kdst;
#pragma unroll
        for (int i = 0; i < 2; i++) {
            cp_async16(kd + (uint32_t)(i * 32 * FLDH * 2), kg + (size_t)(i * 32) * rs);
            cp_async16(vd + (uint32_t)(i * 32 * FLDH * 2), vg + (size_t)(i * 32) * rs);
        }
        cp_arrive_noinc(smb + 8 * s);
    };

    load_kv(0, 0);
    load_kv(1, 1);

    // Stage Q (128 x 64 halves), coalesced 16B stores (Q region untouched by pipeline)
    {
        __half* Qs = (__half*)((char*)smh + QOFF_B);
        int seg = tid & 7, r0 = tid >> 3;
#pragma unroll
        for (int i = 0; i < 4; i++) {
            int r = r0 + i * 32;
            *(uint4*)(Qs + r * FLDH + seg * 8) =
                *(const uint4*)(qptr + (size_t)r * rs + seg * 8);
        }
    }
    __syncthreads();
    uint32_t qf[4][4];
#pragma unroll
    for (int ks = 0; ks < 4; ks++)
        ldmx4(qf[ks][0], qf[ks][1], qf[ks][2], qf[ks][3],
              smb + fqb + (uint32_t)(ks * 16 * 2));

    float mI0 = -INFINITY, mI1 = -INFINITY, lI0 = 0.f, lI1 = 0.f;
    float oacc[8][4];
#pragma unroll
    for (int nf = 0; nf < 8; nf++)
#pragma unroll
        for (int r = 0; r < 4; r++) oacc[nf][r] = 0.f;

    const float scl = 0.125f;
    int fph0 = 0, fph1 = 0, fph2 = 0;
    int eph0 = 0, eph1 = 0, eph2 = 0;

    for (int it = 0; it < nit; it++) {
        const int s = it % 3;
        {
            int* fp = (s == 0) ? &fph0 : (s == 1) ? &fph1 : &fph2;
            mbar_wait(smb + 8 * s, *fp);
            *fp ^= 1;
        }
        const int j = it + 2;
        if (j < nit) {
            const int s2 = j % 3;
            if (j >= 3) {
                int* ep = (s2 == 0) ? &eph0 : (s2 == 1) ? &eph1 : &eph2;
                mbar_wait(smb + 24 + 8 * s2, *ep);
                *ep ^= 1;
            }
            load_kv(j, s2);
        }

        const bool maskedIt = (it >= nit - 2);
        const int k0g = it * FBN;

        // S = Q K^T  (skip fully-masked 8-col groups in masked iters)
        float sa[8][4];
#pragma unroll
        for (int nf = 0; nf < 8; nf++)
#pragma unroll
            for (int r = 0; r < 4; r++) sa[nf][r] = 0.f;

        const uint32_t ksA = stg + (uint32_t)(s * KSTG) * 2;
#pragma unroll
        for (int p = 0; p < 4; p++) {
            if (maskedIt && (k0g + 8 * p > q0 + warp_m + 15)) continue;
#pragma unroll
            for (int ks = 0; ks < 4; ks++) {
                uint32_t k0r, k1r, k2r, k3r;
                ldmx4(k0r, k1r, k2r, k3r,
                      ksA + fkb + (uint32_t)((p * 16 * FLDH + ks * 16) * 2));
                mma_f16(sa[2 * p], qf[ks][0], qf[ks][1], qf[ks][2], qf[ks][3], k0r, k2r);
                mma_f16(sa[2 * p + 1], qf[ks][0], qf[ks][1], qf[ks][2], qf[ks][3], k1r, k3r);
            }
        }

        // scale + causal mask
        if (maskedIt) {
#pragma unroll
            for (int nf = 0; nf < 8; nf++)
#pragma unroll
                for (int r = 0; r < 4; r++) {
                    int i_loc = warp_m + lm + ((r >= 2) ? 8 : 0);
                    int j_loc = nf * 8 + 2 * lk + (r & 1);
                    float v = sa[nf][r] * scl;
                    sa[nf][r] = (k0g + j_loc > q0 + i_loc) ? -INFINITY : v;
                }
        } else {
#pragma unroll
            for (int nf = 0; nf < 8; nf++)
#pragma unroll
                for (int r = 0; r < 4; r++) sa[nf][r] *= scl;
        }

        // online softmax
        float mx0 = -INFINITY, mx1 = -INFINITY;
#pragma unroll
        for (int nf = 0; nf < 8; nf++) {
            mx0 = fmaxf(mx0, fmaxf(sa[nf][0], sa[nf][1]));
            mx1 = fmaxf(mx1, fmaxf(sa[nf][2], sa[nf][3]));
        }
        mx0 = fmaxf(mx0, __shfl_xor_sync(0xffffffffu, mx0, 1));
        mx0 = fmaxf(mx0, __shfl_xor_sync(0xffffffffu, mx0, 2));
        mx1 = fmaxf(mx1, __shfl_xor_sync(0xffffffffu, mx1, 1));
        mx1 = fmaxf(mx1, __shfl_xor_sync(0xffffffffu, mx1, 2));

        float mn0 = fmaxf(mI0, mx0), mn1 = fmaxf(mI1, mx1);
        float c0 = __expf(mI0 - mn0), c1 = __expf(mI1 - mn1);
        float sum0 = 0.f, sum1 = 0.f;
#pragma unroll
        for (int nf = 0; nf < 8; nf++) {
            sa[nf][0] = __expf(sa[nf][0] - mn0);
            sa[nf][1] = __expf(sa[nf][1] - mn0);
            sa[nf][2] = __expf(sa[nf][2] - mn1);
            sa[nf][3] = __expf(sa[nf][3] - mn1);
            sum0 += sa[nf][0] + sa[nf][1];
            sum1 += sa[nf][2] + sa[nf][3];
        }
        sum0 += __shfl_xor_sync(0xffffffffu, sum0, 1);
        sum0 += __shfl_xor_sync(0xffffffffu, sum0, 2);
        sum1 += __shfl_xor_sync(0xffffffffu, sum1, 1);
        sum1 += __shfl_xor_sync(0xffffffffu, sum1, 2);
        lI0 = lI0 * c0 + sum0; mI0 = mn0;
        lI1 = lI1 * c1 + sum1; mI1 = mn1;
#pragma unroll
        for (int nf = 0; nf < 8; nf++) {
            oacc[nf][0] *= c0; oacc[nf][1] *= c0;
            oacc[nf][2] *= c1; oacc[nf][3] *= c1;
        }

        // O += P @ V : P from regs (RN fp16), V via ldmatrix.trans
        const uint32_t vsA = stg + (uint32_t)((3 + s) * KSTG) * 2;
#pragma unroll
        for (int ks = 0; ks < 4; ks++) {
            uint32_t pa0 = pack_h2(sa[2 * ks][0], sa[2 * ks][1]);
            uint32_t pa1 = pack_h2(sa[2 * ks][2], sa[2 * ks][3]);
            uint32_t pa2 = pack_h2(sa[2 * ks + 1][0], sa[2 * ks + 1][1]);
            uint32_t pa3 = pack_h2(sa[2 * ks + 1][2], sa[2 * ks + 1][3]);
#pragma unroll
            for (int p = 0; p < 4; p++) {
                uint32_t v0, v1, v2, v3;
                ldmx4t(v0, v1, v2, v3,
                       vsA + fvb + (uint32_t)((ks * 16 * FLDH + p * 16) * 2));
                mma_f16(oacc[2 * p], pa0, pa1, pa2, pa3, v0, v2);
                mma_f16(oacc[2 * p + 1], pa0, pa1, pa2, pa3, v1, v3);
            }
        }

        __syncwarp();
        if (lane == 0) mbar_arrive(smb + 24 + 8 * s);   // warp done with K/V stage s
    }

    // epilogue: normalize, fp16 RN, write [B*T, C]
    const float inv0 = 1.f / lI0, inv1 = 1.f / lI1;
    const int m0 = q0 + warp_m + lm;
    __half* ob0 = out + (size_t)(b * T_ + m0) * C_ + h * D_;
    __half* ob1 = out + (size_t)(b * T_ + m0 + 8) * C_ + h * D_;
#pragma unroll
    for (int nf = 0; nf < 8; nf++) {
        int cc = nf * 8 + 2 * lk;
        *(uint32_t*)(ob0 + cc) = pack_h2(oacc[nf][0] * inv0, oacc[nf][1] * inv0);
        *(uint32_t*)(ob1 + cc) = pack_h2(oacc[nf][2] * inv1, oacc[nf][3] * inv1);
    }
}

// ---------------------------------------------------------------------------
extern "C" void kernel_launch(void* const* d_in, const int* in_sizes, int n_in,
                              void* d_out, int out_size)
{
    const float* x     = (const float*)d_in[0];
    const float* w_qkv = (const float*)d_in[1];
    const float* w_out = (const float*)d_in[2];
    const float* b_out = (const float*)d_in[3];
    float* out = (float*)d_out;

    __half *qkv_p, *attn_p, *xh_p, *wqkvh_p, *wouth_p;
    cudaGetSymbolAddress((void**)&qkv_p, g_qkvh);
    cudaGetSymbolAddress((void**)&attn_p, g_attnh);
    cudaGetSymbolAddress((void**)&xh_p, g_xh);
    cudaGetSymbolAddress((void**)&wqkvh_p, g_wqkvh);
    cudaGetSymbolAddress((void**)&wouth_p, g_wouth);

    const int M = B_ * T_;

    // 0) fused fp32 -> fp16 (RTN), one launch
    convert_all_kernel<<<(N8_TOT + 255) / 256, 256>>>(
        (const float4*)x, (uint4*)xh_p,
        (const float4*)w_qkv, (uint4*)wqkvh_p,
        (const float4*)w_out, (uint4*)wouth_p);

    cudaFuncSetAttribute(gemm_mma_f16, cudaFuncAttributeMaxDynamicSharedMemorySize, G_SMEM);
    cudaFuncSetAttribute(flash_mma_f16, cudaFuncAttributeMaxDynamicSharedMemorySize, FSM_BYTES);

    // 1) qkv = x @ w_qkv^T  [8192, 3072] -> fp16
    {
        dim3 grid((3 * C_) / G_BN, M / G_BM);
        gemm_mma_f16<<<grid, 256, G_SMEM>>>(xh_p, wqkvh_p, nullptr, nullptr, qkv_p, 3 * C_);
    }

    // 2) flash attention -> g_attnh
    {
        dim3 grid(T_ / FBM, B_ * H_);
        flash_mma_f16<<<grid, 256, FSM_BYTES>>>(qkv_p, attn_p);
    }

    // 3) out = g_attn @ w_out^T + b_out  [8192, 1024] -> fp32
    {
        dim3 grid(C_ / G_BN, M / G_BM);
        gemm_mma_f16<<<grid, 256, G_SMEM>>>(attn_p, wouth_p, b_out, out, nullptr, C_);
    }
}

// round 16
// speedup vs baseline: 1.0291x; 1.0291x over previous
#include <cuda_runtime.h>
#include <cuda_fp16.h>
#include <cstdint>
#include <math.h>

#define B_ 4
#define T_ 2048
#define C_ 1024
#define H_ 16
#define D_ 64

// Scratch (__device__ globals; allocation-free rule)
__device__ __half g_qkvh[(size_t)B_ * T_ * 3 * C_];   // [B*T, 3C] fp16
__device__ __half g_attnh[(size_t)B_ * T_ * C_];      // [B*T, C] fp16
__device__ __half g_xh[(size_t)B_ * T_ * C_];         // fp16 x
__device__ __half g_wqkvh[(size_t)3 * C_ * C_];       // fp16 w_qkv
__device__ __half g_wouth[(size_t)C_ * C_];           // fp16 w_out

// ---------------------------------------------------------------------------
__device__ __forceinline__ uint32_t smem_u32(const void* p) {
    uint32_t a;
    asm("{ .reg .u64 t; cvta.to.shared.u64 t, %1; cvt.u32.u64 %0, t; }" : "=r"(a) : "l"(p));
    return a;
}

__device__ __forceinline__ void cp_async16(uint32_t s, const void* g) {
    asm volatile("cp.async.cg.shared.global [%0], [%1], 16;" :: "r"(s), "l"(g));
}

__device__ __forceinline__ void mma_f16(float c[4], uint32_t a0, uint32_t a1,
                                        uint32_t a2, uint32_t a3,
                                        uint32_t b0, uint32_t b1)
{
    asm volatile(
        "mma.sync.aligned.m16n8k16.row.col.f32.f16.f16.f32 "
        "{%0,%1,%2,%3}, {%4,%5,%6,%7}, {%8,%9}, {%0,%1,%2,%3};"
        : "+f"(c[0]), "+f"(c[1]), "+f"(c[2]), "+f"(c[3])
        : "r"(a0), "r"(a1), "r"(a2), "r"(a3), "r"(b0), "r"(b1));
}

__device__ __forceinline__ void ldmx4(uint32_t& r0, uint32_t& r1, uint32_t& r2,
                                      uint32_t& r3, uint32_t a)
{
    asm volatile("ldmatrix.sync.aligned.m8n8.x4.shared.b16 {%0,%1,%2,%3}, [%4];"
                 : "=r"(r0), "=r"(r1), "=r"(r2), "=r"(r3) : "r"(a));
}

__device__ __forceinline__ void ldmx4t(uint32_t& r0, uint32_t& r1, uint32_t& r2,
                                       uint32_t& r3, uint32_t a)
{
    asm volatile("ldmatrix.sync.aligned.m8n8.x4.trans.shared.b16 {%0,%1,%2,%3}, [%4];"
                 : "=r"(r0), "=r"(r1), "=r"(r2), "=r"(r3) : "r"(a));
}

__device__ __forceinline__ uint32_t pack_h2(float lo, float hi) {
    __half2 h = __floats2half2_rn(lo, hi);
    return *(uint32_t*)&h;
}

__device__ __forceinline__ float ex2(float x) {
    float r;
    asm("ex2.approx.f32 %0, %1;" : "=f"(r) : "f"(x));
    return r;
}

// ---------------------------------------------------------------------------
// fused fp32 -> fp16 (RTN) convert for x, w_qkv, w_out in ONE launch
// ---------------------------------------------------------------------------
#define N8_X  ((B_ * T_ * C_) / 8)
#define N8_WQ ((3 * C_ * C_) / 8)
#define N8_WO ((C_ * C_) / 8)
#define N8_TOT (N8_X + N8_WQ + N8_WO)

__device__ __forceinline__ void cvt8(const float4* in, uint4* out, int i) {
    float4 a = in[2 * i], b = in[2 * i + 1];
    uint4 o;
    o.x = pack_h2(a.x, a.y); o.y = pack_h2(a.z, a.w);
    o.z = pack_h2(b.x, b.y); o.w = pack_h2(b.z, b.w);
    out[i] = o;
}

__global__ __launch_bounds__(256) void convert_all_kernel(
    const float4* __restrict__ x, uint4* __restrict__ xh,
    const float4* __restrict__ wq, uint4* __restrict__ wqh,
    const float4* __restrict__ wo, uint4* __restrict__ woh)
{
    int i = blockIdx.x * blockDim.x + threadIdx.x;
    if (i < N8_X) cvt8(x, xh, i);
    else if (i < N8_X + N8_WQ) cvt8(wq, wqh, i - N8_X);
    else if (i < N8_TOT) cvt8(wo, woh, i - N8_X - N8_WQ);
}

// ---------------------------------------------------------------------------
// fp16 mma.sync GEMM (128x128, BK=64, 3-stage, 2 CTAs/SM), K=1024 hardcoded.
// cp.async issue spread across ks loop. (Round-14 proven structure.)
// ---------------------------------------------------------------------------
#define G_K 1024
#define G_BM 128
#define G_BN 128
#define G_BK 64
#define G_NK (G_K / G_BK)                          // 16
#define G_ST 3
#define G_LDH 72
#define STAGE_H ((G_BM + G_BN) * G_LDH)            // 18432 halves
#define G_SMEM (G_ST * STAGE_H * 2)                // 110592 B

__global__ __launch_bounds__(256, 2) void gemm_mma_f16(
    const __half* __restrict__ A, const __half* __restrict__ Bw,
    const float* __restrict__ bias, float* __restrict__ Cf,
    __half* __restrict__ Ch, int N)
{
    extern __shared__ __half smh[];
    const int tid = threadIdx.x;
    const int lane = tid & 31, wid = tid >> 5;
    const int warp_m = (wid >> 2) * 64;
    const int warp_n = (wid & 3) * 32;
    const int bm = blockIdx.y * G_BM;
    const int bn = blockIdx.x * G_BN;
    const int lm = lane >> 2, lk = lane & 3;
    const int g = lane >> 3, li = lane & 7;

    float c[4][4][4];
#pragma unroll
    for (int mf = 0; mf < 4; mf++)
#pragma unroll
        for (int nf = 0; nf < 4; nf++)
#pragma unroll
            for (int r = 0; r < 4; r++) c[mf][nf][r] = 0.f;

    uint32_t smbase = smem_u32(smh);

    const int crow = tid >> 3, cseg = tid & 7;
    const __half* aBase = A + (size_t)(bm + crow) * G_K + cseg * 8;
    const __half* bBase = Bw + (size_t)(bn + crow) * G_K + cseg * 8;
    const uint32_t dstoff = (uint32_t)((crow * G_LDH + cseg * 8) * 2);

    const uint32_t fa = (uint32_t)(((warp_m + ((g & 1) << 3) + li) * G_LDH + ((g >> 1) << 3)) * 2);
    const uint32_t fb = (uint32_t)(((128 + warp_n + ((g & 1) << 3) + li) * G_LDH + ((g >> 1) << 3)) * 2);

    auto issue_stage = [&](int chunk, int s) {
        uint32_t st = smbase + (uint32_t)(s * STAGE_H) * 2 + dstoff;
        const __half* Ag = aBase + chunk * G_BK;
        const __half* Bg = bBase + chunk * G_BK;
#pragma unroll
        for (int it = 0; it < 4; it++)
            cp_async16(st + (uint32_t)(it * 32 * G_LDH * 2), Ag + it * 32 * G_K);
#pragma unroll
        for (int it = 0; it < 4; it++)
            cp_async16(st + (uint32_t)((128 + it * 32) * G_LDH * 2), Bg + it * 32 * G_K);
    };

#pragma unroll
    for (int s = 0; s < G_ST - 1; s++) {
        issue_stage(s, s);
        asm volatile("cp.async.commit_group;" ::: "memory");
    }

    for (int i = 0; i < G_NK; i++) {
        asm volatile("cp.async.wait_group %0;" :: "n"(G_ST - 2) : "memory");
        __syncthreads();                   // stage i ready; stage (i-1)%ST free

        const bool doLoad = (i + G_ST - 1 < G_NK);
        const uint32_t ldst = smbase +
            (uint32_t)(((i + G_ST - 1) % G_ST) * STAGE_H) * 2 + dstoff;
        const __half* Ag = aBase + (i + G_ST - 1) * G_BK;
        const __half* Bg = bBase + (i + G_ST - 1) * G_BK;

        const uint32_t st = smbase + (uint32_t)((i % G_ST) * STAGE_H) * 2;
#pragma unroll
        for (int ks = 0; ks < 4; ks++) {
            if (doLoad) {   // spread next-stage loads: 2 cp.async per ks
                cp_async16(ldst + (uint32_t)(ks * 32 * G_LDH * 2), Ag + ks * 32 * G_K);
                cp_async16(ldst + (uint32_t)((128 + ks * 32) * G_LDH * 2), Bg + ks * 32 * G_K);
            }
            uint32_t a[4][4], b0[2], b1[2], b2[2], b3[2];
#pragma unroll
            for (int mf = 0; mf < 4; mf++)
                ldmx4(a[mf][0], a[mf][1], a[mf][2], a[mf][3],
                      st + fa + (uint32_t)((mf * 16 * G_LDH + ks * 16) * 2));
#pragma unroll
            for (int p = 0; p < 2; p++)
                ldmx4(b0[p], b1[p], b2[p], b3[p],
                      st + fb + (uint32_t)((p * 16 * G_LDH + ks * 16) * 2));
#pragma unroll
            for (int mf = 0; mf < 4; mf++)
#pragma unroll
                for (int p = 0; p < 2; p++) {
                    mma_f16(c[mf][2 * p], a[mf][0], a[mf][1], a[mf][2], a[mf][3],
                            b0[p], b2[p]);
                    mma_f16(c[mf][2 * p + 1], a[mf][0], a[mf][1], a[mf][2], a[mf][3],
                            b1[p], b3[p]);
                }
        }
        asm volatile("cp.async.commit_group;" ::: "memory");
    }

#pragma unroll
    for (int mf = 0; mf < 4; mf++) {
        int m = bm + warp_m + mf * 16 + lm;
#pragma unroll
        for (int nf = 0; nf < 4; nf++) {
            int n = bn + warp_n + nf * 8 + 2 * lk;
            if (Ch) {
                *(uint32_t*)(Ch + (size_t)m * N + n) = pack_h2(c[mf][nf][0], c[mf][nf][1]);
                *(uint32_t*)(Ch + (size_t)(m + 8) * N + n) = pack_h2(c[mf][nf][2], c[mf][nf][3]);
            } else {
                float bx = bias ? bias[n] : 0.f, by = bias ? bias[n + 1] : 0.f;
                *(float2*)(Cf + (size_t)m * N + n) =
                    make_float2(c[mf][nf][0] + bx, c[mf][nf][1] + by);
                *(float2*)(Cf + (size_t)(m + 8) * N + n) =
                    make_float2(c[mf][nf][2] + bx, c[mf][nf][3] + by);
            }
        }
    }
}

// ---------------------------------------------------------------------------
// Flash attention (BM=128, BN=64, 8 warps, 2 CTAs/SM). Round-14 structure
// + PV mask-skip (skip zero-P k-chunks in masked iters) + base-2 softmax
// (scale*log2e folded into the one post-mma multiply; raw ex2.approx).
// ---------------------------------------------------------------------------
#define FBM 128
#define FBN 64
#define FLDH 72
#define KSTG (64 * FLDH)
#define QOFF (6 * KSTG)
#define FSM_H (QOFF + 128 * FLDH)
#define FSM_BYTES (FSM_H * 2)              // 73728 B

__global__ __launch_bounds__(256, 2) void flash_mma_f16(
    const __half* __restrict__ qkv, __half* __restrict__ out)
{
    extern __shared__ __half smh[];
    const int tid = threadIdx.x, lane = tid & 31, wid = tid >> 5;
    const int lm = lane >> 2, lk = lane & 3;
    const int g = lane >> 3, li = lane & 7;
    const int warp_m = wid * 16;
    const int qtile = gridDim.x - 1 - blockIdx.x;    // heavy tiles first
    const int q0 = qtile * FBM;
    const int bh = blockIdx.y;
    const int b = bh >> 4, h = bh & 15;
    const size_t rs = 3 * C_;

    const __half* qptr = qkv + (size_t)(b * T_ + q0) * rs + h * D_;

    uint32_t smb = smem_u32(smh);
    const int nit = q0 / FBN + 2;

    const int crow = tid >> 3, cseg = tid & 7;
    const __half* kBase = qkv + (size_t)(b * T_ + crow) * rs + C_ + h * D_ + cseg * 8;
    const __half* vBase = kBase + C_;
    const uint32_t kdst = (uint32_t)((crow * FLDH + cseg * 8) * 2);

    const uint32_t fkb = (uint32_t)(((((g & 1) << 3) + li) * FLDH + ((g >> 1) << 3)) * 2);
    const uint32_t fvb = (uint32_t)(((((g >> 1) << 3) + li) * FLDH + ((g & 1) << 3)) * 2);
    const uint32_t fqb = (uint32_t)(QOFF * 2) +
        (uint32_t)(((warp_m + ((g & 1) << 3) + li) * FLDH + ((g >> 1) << 3)) * 2);

    auto load_kv = [&](int it, int s) {
        const __half* kg = kBase + (size_t)(it * FBN) * rs;
        const __half* vg = vBase + (size_t)(it * FBN) * rs;
        uint32_t kd = smb + (uint32_t)(s * KSTG) * 2 + kdst;
        uint32_t vd = smb + (uint32_t)((3 + s) * KSTG) * 2 + kdst;
#pragma unroll
        for (int i = 0; i < 2; i++) {
            cp_async16(kd + (uint32_t)(i * 32 * FLDH * 2), kg + (size_t)(i * 32) * rs);
            cp_async16(vd + (uint32_t)(i * 32 * FLDH * 2), vg + (size_t)(i * 32) * rs);
        }
    };

    load_kv(0, 0);
    asm volatile("cp.async.commit_group;" ::: "memory");
    load_kv(1, 1);
    asm volatile("cp.async.commit_group;" ::: "memory");

    {
        int seg = tid & 7, r0 = tid >> 3;
#pragma unroll
        for (int i = 0; i < 4; i++) {
            int r = r0 + i * 32;
            *(uint4*)(smh + QOFF + r * FLDH + seg * 8) =
                *(const uint4*)(qptr + (size_t)r * rs + seg * 8);
        }
    }
    __syncthreads();
    uint32_t qf[4][4];
#pragma unroll
    for (int ks = 0; ks < 4; ks++)
        ldmx4(qf[ks][0], qf[ks][1], qf[ks][2], qf[ks][3],
              smb + fqb + (uint32_t)(ks * 16 * 2));

    float mI0 = -INFINITY, mI1 = -INFINITY, lI0 = 0.f, lI1 = 0.f;
    float oacc[8][4];
#pragma unroll
    for (int nf = 0; nf < 8; nf++)
#pragma unroll
        for (int r = 0; r < 4; r++) oacc[nf][r] = 0.f;

    // base-2 softmax: 2^(s*scl2) == e^(s*0.125);  scl2 = 0.125*log2(e)
    const float scl2 = 0.18033688011112042f;

    for (int it = 0; it < nit; it++) {
        const int s = it % 3;
        asm volatile("cp.async.wait_group 1;" ::: "memory");
        __syncthreads();
        if (it + 2 < nit) load_kv(it + 2, (it + 2) % 3);
        asm volatile("cp.async.commit_group;" ::: "memory");

        const bool maskedIt = (it >= nit - 2);
        const int k0g = it * FBN;
        const int lastValid = q0 + warp_m + 15;   // max kv col with any unmasked P in this warp

        // S = Q K^T  (skip fully-masked 8-col groups in masked iters)
        float sa[8][4];
#pragma unroll
        for (int nf = 0; nf < 8; nf++)
#pragma unroll
            for (int r = 0; r < 4; r++) sa[nf][r] = 0.f;

        const uint32_t ksA = smb + (uint32_t)(s * KSTG) * 2;
#pragma unroll
        for (int p = 0; p < 4; p++) {
            if (maskedIt && (k0g + 8 * p > lastValid)) continue;
#pragma unroll
            for (int ks = 0; ks < 4; ks++) {
                uint32_t k0r, k1r, k2r, k3r;
                ldmx4(k0r, k1r, k2r, k3r,
                      ksA + fkb + (uint32_t)((p * 16 * FLDH + ks * 16) * 2));
                mma_f16(sa[2 * p], qf[ks][0], qf[ks][1], qf[ks][2], qf[ks][3], k0r, k2r);
                mma_f16(sa[2 * p + 1], qf[ks][0], qf[ks][1], qf[ks][2], qf[ks][3], k1r, k3r);
            }
        }

        // scale (base-2 domain) + causal mask
        if (maskedIt) {
#pragma unroll
            for (int nf = 0; nf < 8; nf++)
#pragma unroll
                for (int r = 0; r < 4; r++) {
                    int i_loc = warp_m + lm + ((r >= 2) ? 8 : 0);
                    int j_loc = nf * 8 + 2 * lk + (r & 1);
                    float v = sa[nf][r] * scl2;
                    sa[nf][r] = (k0g + j_loc > q0 + i_loc) ? -INFINITY : v;
                }
        } else {
#pragma unroll
            for (int nf = 0; nf < 8; nf++)
#pragma unroll
                for (int r = 0; r < 4; r++) sa[nf][r] *= scl2;
        }

        // online softmax (base 2)
        float mx0 = -INFINITY, mx1 = -INFINITY;
#pragma unroll
        for (int nf = 0; nf < 8; nf++) {
            mx0 = fmaxf(mx0, fmaxf(sa[nf][0], sa[nf][1]));
            mx1 = fmaxf(mx1, fmaxf(sa[nf][2], sa[nf][3]));
        }
        mx0 = fmaxf(mx0, __shfl_xor_sync(0xffffffffu, mx0, 1));
        mx0 = fmaxf(mx0, __shfl_xor_sync(0xffffffffu, mx0, 2));
        mx1 = fmaxf(mx1, __shfl_xor_sync(0xffffffffu, mx1, 1));
        mx1 = fmaxf(mx1, __shfl_xor_sync(0xffffffffu, mx1, 2));

        float mn0 = fmaxf(mI0, mx0), mn1 = fmaxf(mI1, mx1);
        float c0 = ex2(mI0 - mn0), c1 = ex2(mI1 - mn1);
        float sum0 = 0.f, sum1 = 0.f;
#pragma unroll
        for (int nf = 0; nf < 8; nf++) {
            sa[nf][0] = ex2(sa[nf][0] - mn0);
            sa[nf][1] = ex2(sa[nf][1] - mn0);
            sa[nf][2] = ex2(sa[nf][2] - mn1);
            sa[nf][3] = ex2(sa[nf][3] - mn1);
            sum0 += sa[nf][0] + sa[nf][1];
            sum1 += sa[nf][2] + sa[nf][3];
        }
        sum0 += __shfl_xor_sync(0xffffffffu, sum0, 1);
        sum0 += __shfl_xor_sync(0xffffffffu, sum0, 2);
        sum1 += __shfl_xor_sync(0xffffffffu, sum1, 1);
        sum1 += __shfl_xor_sync(0xffffffffu, sum1, 2);
        lI0 = lI0 * c0 + sum0; mI0 = mn0;
        lI1 = lI1 * c1 + sum1; mI1 = mn1;
#pragma unroll
        for (int nf = 0; nf < 8; nf++) {
            oacc[nf][0] *= c0; oacc[nf][1] *= c0;
            oacc[nf][2] *= c1; oacc[nf][3] *= c1;
        }

        // O += P @ V : P from regs (RN fp16), V via ldmatrix.trans.
        // In masked iters, skip k-chunks whose P columns are all zero.
        const uint32_t vsA = smb + (uint32_t)((3 + s) * KSTG) * 2;
#pragma unroll
        for (int ks = 0; ks < 4; ks++) {
            if (maskedIt && (k0g + 16 * ks > lastValid)) continue;   // P chunk all-zero
            uint32_t pa0 = pack_h2(sa[2 * ks][0], sa[2 * ks][1]);
            uint32_t pa1 = pack_h2(sa[2 * ks][2], sa[2 * ks][3]);
            uint32_t pa2 = pack_h2(sa[2 * ks + 1][0], sa[2 * ks + 1][1]);
            uint32_t pa3 = pack_h2(sa[2 * ks + 1][2], sa[2 * ks + 1][3]);
#pragma unroll
            for (int p = 0; p < 4; p++) {
                uint32_t v0, v1, v2, v3;
                ldmx4t(v0, v1, v2, v3,
                       vsA + fvb + (uint32_t)((ks * 16 * FLDH + p * 16) * 2));
                mma_f16(oacc[2 * p], pa0, pa1, pa2, pa3, v0, v2);
                mma_f16(oacc[2 * p + 1], pa0, pa1, pa2, pa3, v1, v3);
            }
        }
    }

    // epilogue: normalize, fp16 RN, write [B*T, C]
    const float inv0 = 1.f / lI0, inv1 = 1.f / lI1;
    const int m0 = q0 + warp_m + lm;
    __half* ob0 = out + (size_t)(b * T_ + m0) * C_ + h * D_;
    __half* ob1 = out + (size_t)(b * T_ + m0 + 8) * C_ + h * D_;
#pragma unroll
    for (int nf = 0; nf < 8; nf++) {
        int cc = nf * 8 + 2 * lk;
        *(uint32_t*)(ob0 + cc) = pack_h2(oacc[nf][0] * inv0, oacc[nf][1] * inv0);
        *(uint32_t*)(ob1 + cc) = pack_h2(oacc[nf][2] * inv1, oacc[nf][3] * inv1);
    }
}

// ---------------------------------------------------------------------------
extern "C" void kernel_launch(void* const* d_in, const int* in_sizes, int n_in,
                              void* d_out, int out_size)
{
    const float* x     = (const float*)d_in[0];
    const float* w_qkv = (const float*)d_in[1];
    const float* w_out = (const float*)d_in[2];
    const float* b_out = (const float*)d_in[3];
    float* out = (float*)d_out;

    __half *qkv_p, *attn_p, *xh_p, *wqkvh_p, *wouth_p;
    cudaGetSymbolAddress((void**)&qkv_p, g_qkvh);
    cudaGetSymbolAddress((void**)&attn_p, g_attnh);
    cudaGetSymbolAddress((void**)&xh_p, g_xh);
    cudaGetSymbolAddress((void**)&wqkvh_p, g_wqkvh);
    cudaGetSymbolAddress((void**)&wouth_p, g_wouth);

    const int M = B_ * T_;

    // 0) fused fp32 -> fp16 (RTN), one launch
    convert_all_kernel<<<(N8_TOT + 255) / 256, 256>>>(
        (const float4*)x, (uint4*)xh_p,
        (const float4*)w_qkv, (uint4*)wqkvh_p,
        (const float4*)w_out, (uint4*)wouth_p);

    cudaFuncSetAttribute(gemm_mma_f16, cudaFuncAttributeMaxDynamicSharedMemorySize, G_SMEM);
    cudaFuncSetAttribute(flash_mma_f16, cudaFuncAttributeMaxDynamicSharedMemorySize, FSM_BYTES);

    // 1) qkv = x @ w_qkv^T  [8192, 3072] -> fp16
    {
        dim3 grid((3 * C_) / G_BN, M / G_BM);
        gemm_mma_f16<<<grid, 256, G_SMEM>>>(xh_p, wqkvh_p, nullptr, nullptr, qkv_p, 3 * C_);
    }

    // 2) flash attention -> g_attnh
    {
        dim3 grid(T_ / FBM, B_ * H_);
        flash_mma_f16<<<grid, 256, FSM_BYTES>>>(qkv_p, attn_p);
    }

    // 3) out = g_attn @ w_out^T + b_out  [8192, 1024] -> fp32
    {
        dim3 grid(C_ / G_BN, M / G_BM);
        gemm_mma_f16<<<grid, 256, G_SMEM>>>(attn_p, wouth_p, b_out, out, nullptr, C_);
    }
}

// round 17
// speedup vs baseline: 1.0448x; 1.0152x over previous
#include <cuda_runtime.h>
#include <cuda_fp16.h>
#include <cstdint>
#include <math.h>

#define B_ 4
#define T_ 2048
#define C_ 1024
#define H_ 16
#define D_ 64

// Scratch (__device__ globals; allocation-free rule)
__device__ __half g_qkvh[(size_t)B_ * T_ * 3 * C_];   // [B*T, 3C] fp16
__device__ __half g_attnh[(size_t)B_ * T_ * C_];      // [B*T, C] fp16
__device__ __half g_xh[(size_t)B_ * T_ * C_];         // fp16 x
__device__ __half g_wqkvh[(size_t)3 * C_ * C_];       // fp16 w_qkv
__device__ __half g_wouth[(size_t)C_ * C_];           // fp16 w_out

// ---------------------------------------------------------------------------
__device__ __forceinline__ uint32_t smem_u32(const void* p) {
    uint32_t a;
    asm("{ .reg .u64 t; cvta.to.shared.u64 t, %1; cvt.u32.u64 %0, t; }" : "=r"(a) : "l"(p));
    return a;
}

__device__ __forceinline__ void cp_async16(uint32_t s, const void* g) {
    asm volatile("cp.async.cg.shared.global [%0], [%1], 16;" :: "r"(s), "l"(g));
}

__device__ __forceinline__ void mma_f16(float c[4], uint32_t a0, uint32_t a1,
                                        uint32_t a2, uint32_t a3,
                                        uint32_t b0, uint32_t b1)
{
    asm volatile(
        "mma.sync.aligned.m16n8k16.row.col.f32.f16.f16.f32 "
        "{%0,%1,%2,%3}, {%4,%5,%6,%7}, {%8,%9}, {%0,%1,%2,%3};"
        : "+f"(c[0]), "+f"(c[1]), "+f"(c[2]), "+f"(c[3])
        : "r"(a0), "r"(a1), "r"(a2), "r"(a3), "r"(b0), "r"(b1));
}

__device__ __forceinline__ void ldmx4(uint32_t& r0, uint32_t& r1, uint32_t& r2,
                                      uint32_t& r3, uint32_t a)
{
    asm volatile("ldmatrix.sync.aligned.m8n8.x4.shared.b16 {%0,%1,%2,%3}, [%4];"
                 : "=r"(r0), "=r"(r1), "=r"(r2), "=r"(r3) : "r"(a));
}

__device__ __forceinline__ void ldmx4t(uint32_t& r0, uint32_t& r1, uint32_t& r2,
                                       uint32_t& r3, uint32_t a)
{
    asm volatile("ldmatrix.sync.aligned.m8n8.x4.trans.shared.b16 {%0,%1,%2,%3}, [%4];"
                 : "=r"(r0), "=r"(r1), "=r"(r2), "=r"(r3) : "r"(a));
}

__device__ __forceinline__ uint32_t pack_h2(float lo, float hi) {
    __half2 h = __floats2half2_rn(lo, hi);
    return *(uint32_t*)&h;
}

__device__ __forceinline__ float ex2(float x) {
    float r;
    asm("ex2.approx.f32 %0, %1;" : "=f"(r) : "f"(x));
    return r;
}

// ---------------------------------------------------------------------------
// fused fp32 -> fp16 (RTN) convert for x, w_qkv, w_out in ONE launch
// ---------------------------------------------------------------------------
#define N8_X  ((B_ * T_ * C_) / 8)
#define N8_WQ ((3 * C_ * C_) / 8)
#define N8_WO ((C_ * C_) / 8)
#define N8_TOT (N8_X + N8_WQ + N8_WO)

__device__ __forceinline__ void cvt8(const float4* in, uint4* out, int i) {
    float4 a = in[2 * i], b = in[2 * i + 1];
    uint4 o;
    o.x = pack_h2(a.x, a.y); o.y = pack_h2(a.z, a.w);
    o.z = pack_h2(b.x, b.y); o.w = pack_h2(b.z, b.w);
    out[i] = o;
}

__global__ __launch_bounds__(256) void convert_all_kernel(
    const float4* __restrict__ x, uint4* __restrict__ xh,
    const float4* __restrict__ wq, uint4* __restrict__ wqh,
    const float4* __restrict__ wo, uint4* __restrict__ woh)
{
    int i = blockIdx.x * blockDim.x + threadIdx.x;
    if (i < N8_X) cvt8(x, xh, i);
    else if (i < N8_X + N8_WQ) cvt8(wq, wqh, i - N8_X);
    else if (i < N8_TOT) cvt8(wo, woh, i - N8_X - N8_WQ);
}

// ---------------------------------------------------------------------------
// fp16 mma.sync GEMM (128x128, BK=64, 3-stage, 2 CTAs/SM), K=1024 hardcoded.
// cp.async issue spread across ks loop. (Round-14/16 proven; at HMMA ceiling.)
// ---------------------------------------------------------------------------
#define G_K 1024
#define G_BM 128
#define G_BN 128
#define G_BK 64
#define G_NK (G_K / G_BK)                          // 16
#define G_ST 3
#define G_LDH 72
#define STAGE_H ((G_BM + G_BN) * G_LDH)            // 18432 halves
#define G_SMEM (G_ST * STAGE_H * 2)                // 110592 B

__global__ __launch_bounds__(256, 2) void gemm_mma_f16(
    const __half* __restrict__ A, const __half* __restrict__ Bw,
    const float* __restrict__ bias, float* __restrict__ Cf,
    __half* __restrict__ Ch, int N)
{
    extern __shared__ __half smh[];
    const int tid = threadIdx.x;
    const int lane = tid & 31, wid = tid >> 5;
    const int warp_m = (wid >> 2) * 64;
    const int warp_n = (wid & 3) * 32;
    const int bm = blockIdx.y * G_BM;
    const int bn = blockIdx.x * G_BN;
    const int lm = lane >> 2, lk = lane & 3;
    const int g = lane >> 3, li = lane & 7;

    float c[4][4][4];
#pragma unroll
    for (int mf = 0; mf < 4; mf++)
#pragma unroll
        for (int nf = 0; nf < 4; nf++)
#pragma unroll
            for (int r = 0; r < 4; r++) c[mf][nf][r] = 0.f;

    uint32_t smbase = smem_u32(smh);

    const int crow = tid >> 3, cseg = tid & 7;
    const __half* aBase = A + (size_t)(bm + crow) * G_K + cseg * 8;
    const __half* bBase = Bw + (size_t)(bn + crow) * G_K + cseg * 8;
    const uint32_t dstoff = (uint32_t)((crow * G_LDH + cseg * 8) * 2);

    const uint32_t fa = (uint32_t)(((warp_m + ((g & 1) << 3) + li) * G_LDH + ((g >> 1) << 3)) * 2);
    const uint32_t fb = (uint32_t)(((128 + warp_n + ((g & 1) << 3) + li) * G_LDH + ((g >> 1) << 3)) * 2);

    auto issue_stage = [&](int chunk, int s) {
        uint32_t st = smbase + (uint32_t)(s * STAGE_H) * 2 + dstoff;
        const __half* Ag = aBase + chunk * G_BK;
        const __half* Bg = bBase + chunk * G_BK;
#pragma unroll
        for (int it = 0; it < 4; it++)
            cp_async16(st + (uint32_t)(it * 32 * G_LDH * 2), Ag + it * 32 * G_K);
#pragma unroll
        for (int it = 0; it < 4; it++)
            cp_async16(st + (uint32_t)((128 + it * 32) * G_LDH * 2), Bg + it * 32 * G_K);
    };

#pragma unroll
    for (int s = 0; s < G_ST - 1; s++) {
        issue_stage(s, s);
        asm volatile("cp.async.commit_group;" ::: "memory");
    }

    for (int i = 0; i < G_NK; i++) {
        asm volatile("cp.async.wait_group %0;" :: "n"(G_ST - 2) : "memory");
        __syncthreads();                   // stage i ready; stage (i-1)%ST free

        const bool doLoad = (i + G_ST - 1 < G_NK);
        const uint32_t ldst = smbase +
            (uint32_t)(((i + G_ST - 1) % G_ST) * STAGE_H) * 2 + dstoff;
        const __half* Ag = aBase + (i + G_ST - 1) * G_BK;
        const __half* Bg = bBase + (i + G_ST - 1) * G_BK;

        const uint32_t st = smbase + (uint32_t)((i % G_ST) * STAGE_H) * 2;
#pragma unroll
        for (int ks = 0; ks < 4; ks++) {
            if (doLoad) {   // spread next-stage loads: 2 cp.async per ks
                cp_async16(ldst + (uint32_t)(ks * 32 * G_LDH * 2), Ag + ks * 32 * G_K);
                cp_async16(ldst + (uint32_t)((128 + ks * 32) * G_LDH * 2), Bg + ks * 32 * G_K);
            }
            uint32_t a[4][4], b0[2], b1[2], b2[2], b3[2];
#pragma unroll
            for (int mf = 0; mf < 4; mf++)
                ldmx4(a[mf][0], a[mf][1], a[mf][2], a[mf][3],
                      st + fa + (uint32_t)((mf * 16 * G_LDH + ks * 16) * 2));
#pragma unroll
            for (int p = 0; p < 2; p++)
                ldmx4(b0[p], b1[p], b2[p], b3[p],
                      st + fb + (uint32_t)((p * 16 * G_LDH + ks * 16) * 2));
#pragma unroll
            for (int mf = 0; mf < 4; mf++)
#pragma unroll
                for (int p = 0; p < 2; p++) {
                    mma_f16(c[mf][2 * p], a[mf][0], a[mf][1], a[mf][2], a[mf][3],
                            b0[p], b2[p]);
                    mma_f16(c[mf][2 * p + 1], a[mf][0], a[mf][1], a[mf][2], a[mf][3],
                            b1[p], b3[p]);
                }
        }
        asm volatile("cp.async.commit_group;" ::: "memory");
    }

#pragma unroll
    for (int mf = 0; mf < 4; mf++) {
        int m = bm + warp_m + mf * 16 + lm;
#pragma unroll
        for (int nf = 0; nf < 4; nf++) {
            int n = bn + warp_n + nf * 8 + 2 * lk;
            if (Ch) {
                *(uint32_t*)(Ch + (size_t)m * N + n) = pack_h2(c[mf][nf][0], c[mf][nf][1]);
                *(uint32_t*)(Ch + (size_t)(m + 8) * N + n) = pack_h2(c[mf][nf][2], c[mf][nf][3]);
            } else {
                float bx = bias ? bias[n] : 0.f, by = bias ? bias[n + 1] : 0.f;
                *(float2*)(Cf + (size_t)m * N + n) =
                    make_float2(c[mf][nf][0] + bx, c[mf][nf][1] + by);
                *(float2*)(Cf + (size_t)(m + 8) * N + n) =
                    make_float2(c[mf][nf][2] + bx, c[mf][nf][3] + by);
            }
        }
    }
}

// ---------------------------------------------------------------------------
// Flash attention (BM=128, BN=64, 8 warps, 2 CTAs/SM). 4-stage K/V pipeline
// (wait_group 2), raw-domain max + scale folded into the exp FMA (no scaling
// pass), S/PV mask-skips, base-2 softmax.
// ---------------------------------------------------------------------------
#define FBM 128
#define FBN 64
#define FLDH 72
#define FST 4
#define KSTG (64 * FLDH)
#define QOFF (2 * FST * KSTG)                  // after 4 K + 4 V stages
#define FSM_H (QOFF + 128 * FLDH)              // 46080 halves
#define FSM_BYTES (FSM_H * 2)                  // 92160 B

__global__ __launch_bounds__(256, 2) void flash_mma_f16(
    const __half* __restrict__ qkv, __half* __restrict__ out)
{
    extern __shared__ __half smh[];
    const int tid = threadIdx.x, lane = tid & 31, wid = tid >> 5;
    const int lm = lane >> 2, lk = lane & 3;
    const int g = lane >> 3, li = lane & 7;
    const int warp_m = wid * 16;
    const int qtile = gridDim.x - 1 - blockIdx.x;    // heavy tiles first
    const int q0 = qtile * FBM;
    const int bh = blockIdx.y;
    const int b = bh >> 4, h = bh & 15;
    const size_t rs = 3 * C_;

    const __half* qptr = qkv + (size_t)(b * T_ + q0) * rs + h * D_;

    uint32_t smb = smem_u32(smh);
    const int nit = q0 / FBN + 2;

    const int crow = tid >> 3, cseg = tid & 7;
    const __half* kBase = qkv + (size_t)(b * T_ + crow) * rs + C_ + h * D_ + cseg * 8;
    const __half* vBase = kBase + C_;
    const uint32_t kdst = (uint32_t)((crow * FLDH + cseg * 8) * 2);

    const uint32_t fkb = (uint32_t)(((((g & 1) << 3) + li) * FLDH + ((g >> 1) << 3)) * 2);
    const uint32_t fvb = (uint32_t)(((((g >> 1) << 3) + li) * FLDH + ((g & 1) << 3)) * 2);
    const uint32_t fqb = (uint32_t)(QOFF * 2) +
        (uint32_t)(((warp_m + ((g & 1) << 3) + li) * FLDH + ((g >> 1) << 3)) * 2);

    auto load_kv = [&](int it, int s) {
        const __half* kg = kBase + (size_t)(it * FBN) * rs;
        const __half* vg = vBase + (size_t)(it * FBN) * rs;
        uint32_t kd = smb + (uint32_t)(s * KSTG) * 2 + kdst;
        uint32_t vd = smb + (uint32_t)((FST + s) * KSTG) * 2 + kdst;
#pragma unroll
        for (int i = 0; i < 2; i++) {
            cp_async16(kd + (uint32_t)(i * 32 * FLDH * 2), kg + (size_t)(i * 32) * rs);
            cp_async16(vd + (uint32_t)(i * 32 * FLDH * 2), vg + (size_t)(i * 32) * rs);
        }
    };

    // prologue: 3 committed groups (empty commits keep the accounting exact)
#pragma unroll
    for (int c = 0; c < 3; c++) {
        if (c < nit) load_kv(c, c);
        asm volatile("cp.async.commit_group;" ::: "memory");
    }

    {
        int seg = tid & 7, r0 = tid >> 3;
#pragma unroll
        for (int i = 0; i < 4; i++) {
            int r = r0 + i * 32;
            *(uint4*)(smh + QOFF + r * FLDH + seg * 8) =
                *(const uint4*)(qptr + (size_t)r * rs + seg * 8);
        }
    }
    __syncthreads();
    uint32_t qf[4][4];
#pragma unroll
    for (int ks = 0; ks < 4; ks++)
        ldmx4(qf[ks][0], qf[ks][1], qf[ks][2], qf[ks][3],
              smb + fqb + (uint32_t)(ks * 16 * 2));

    float mI0 = -INFINITY, mI1 = -INFINITY, lI0 = 0.f, lI1 = 0.f;
    float oacc[8][4];
#pragma unroll
    for (int nf = 0; nf < 8; nf++)
#pragma unroll
        for (int r = 0; r < 4; r++) oacc[nf][r] = 0.f;

    // base-2 softmax: 2^(s*scl2) == e^(s*0.125)
    const float scl2 = 0.18033688011112042f;

    for (int it = 0; it < nit; it++) {
        const int s = it & (FST - 1);
        asm volatile("cp.async.wait_group 2;" ::: "memory");   // chunk it done
        __syncthreads();                                       // stage (it-1)%4 free
        if (it + 3 < nit) load_kv(it + 3, (it + 3) & (FST - 1));
        asm volatile("cp.async.commit_group;" ::: "memory");

        const bool maskedIt = (it >= nit - 2);
        const int k0g = it * FBN;
        const int lastValid = q0 + warp_m + 15;

        // S = Q K^T  (raw domain; skip fully-masked 8-col groups)
        float sa[8][4];
#pragma unroll
        for (int nf = 0; nf < 8; nf++)
#pragma unroll
            for (int r = 0; r < 4; r++) sa[nf][r] = 0.f;

        const uint32_t ksA = smb + (uint32_t)(s * KSTG) * 2;
#pragma unroll
        for (int p = 0; p < 4; p++) {
            if (maskedIt && (k0g + 8 * p > lastValid)) continue;
#pragma unroll
            for (int ks = 0; ks < 4; ks++) {
                uint32_t k0r, k1r, k2r, k3r;
                ldmx4(k0r, k1r, k2r, k3r,
                      ksA + fkb + (uint32_t)((p * 16 * FLDH + ks * 16) * 2));
                mma_f16(sa[2 * p], qf[ks][0], qf[ks][1], qf[ks][2], qf[ks][3], k0r, k2r);
                mma_f16(sa[2 * p + 1], qf[ks][0], qf[ks][1], qf[ks][2], qf[ks][3], k1r, k3r);
            }
        }

        // causal mask on RAW values (no scaling pass; scl2 folds into exp FMA)
        if (maskedIt) {
#pragma unroll
            for (int nf = 0; nf < 8; nf++)
#pragma unroll
                for (int r = 0; r < 4; r++) {
                    int i_loc = warp_m + lm + ((r >= 2) ? 8 : 0);
                    int j_loc = nf * 8 + 2 * lk + (r & 1);
                    if (k0g + j_loc > q0 + i_loc) sa[nf][r] = -INFINITY;
                }
        }

        // online softmax (max in raw domain, scaled once per row)
        float mx0 = -INFINITY, mx1 = -INFINITY;
#pragma unroll
        for (int nf = 0; nf < 8; nf++) {
            mx0 = fmaxf(mx0, fmaxf(sa[nf][0], sa[nf][1]));
            mx1 = fmaxf(mx1, fmaxf(sa[nf][2], sa[nf][3]));
        }
        mx0 = fmaxf(mx0, __shfl_xor_sync(0xffffffffu, mx0, 1));
        mx0 = fmaxf(mx0, __shfl_xor_sync(0xffffffffu, mx0, 2));
        mx1 = fmaxf(mx1, __shfl_xor_sync(0xffffffffu, mx1, 1));
        mx1 = fmaxf(mx1, __shfl_xor_sync(0xffffffffu, mx1, 2));

        float mn0 = fmaxf(mI0, mx0 * scl2), mn1 = fmaxf(mI1, mx1 * scl2);
        float c0 = ex2(mI0 - mn0), c1 = ex2(mI1 - mn1);
        float sum0 = 0.f, sum1 = 0.f;
#pragma unroll
        for (int nf = 0; nf < 8; nf++) {
            sa[nf][0] = ex2(fmaf(sa[nf][0], scl2, -mn0));
            sa[nf][1] = ex2(fmaf(sa[nf][1], scl2, -mn0));
            sa[nf][2] = ex2(fmaf(sa[nf][2], scl2, -mn1));
            sa[nf][3] = ex2(fmaf(sa[nf][3], scl2, -mn1));
            sum0 += sa[nf][0] + sa[nf][1];
            sum1 += sa[nf][2] + sa[nf][3];
        }
        sum0 += __shfl_xor_sync(0xffffffffu, sum0, 1);
        sum0 += __shfl_xor_sync(0xffffffffu, sum0, 2);
        sum1 += __shfl_xor_sync(0xffffffffu, sum1, 1);
        sum1 += __shfl_xor_sync(0xffffffffu, sum1, 2);
        lI0 = lI0 * c0 + sum0; mI0 = mn0;
        lI1 = lI1 * c1 + sum1; mI1 = mn1;
#pragma unroll
        for (int nf = 0; nf < 8; nf++) {
            oacc[nf][0] *= c0; oacc[nf][1] *= c0;
            oacc[nf][2] *= c1; oacc[nf][3] *= c1;
        }

        // O += P @ V (skip all-zero P k-chunks in masked iters)
        const uint32_t vsA = smb + (uint32_t)((FST + s) * KSTG) * 2;
#pragma unroll
        for (int ks = 0; ks < 4; ks++) {
            if (maskedIt && (k0g + 16 * ks > lastValid)) continue;
            uint32_t pa0 = pack_h2(sa[2 * ks][0], sa[2 * ks][1]);
            uint32_t pa1 = pack_h2(sa[2 * ks][2], sa[2 * ks][3]);
            uint32_t pa2 = pack_h2(sa[2 * ks + 1][0], sa[2 * ks + 1][1]);
            uint32_t pa3 = pack_h2(sa[2 * ks + 1][2], sa[2 * ks + 1][3]);
#pragma unroll
            for (int p = 0; p < 4; p++) {
                uint32_t v0, v1, v2, v3;
                ldmx4t(v0, v1, v2, v3,
                       vsA + fvb + (uint32_t)((ks * 16 * FLDH + p * 16) * 2));
                mma_f16(oacc[2 * p], pa0, pa1, pa2, pa3, v0, v2);
                mma_f16(oacc[2 * p + 1], pa0, pa1, pa2, pa3, v1, v3);
            }
        }
    }

    // epilogue: normalize, fp16 RN, write [B*T, C]
    const float inv0 = 1.f / lI0, inv1 = 1.f / lI1;
    const int m0 = q0 + warp_m + lm;
    __half* ob0 = out + (size_t)(b * T_ + m0) * C_ + h * D_;
    __half* ob1 = out + (size_t)(b * T_ + m0 + 8) * C_ + h * D_;
#pragma unroll
    for (int nf = 0; nf < 8; nf++) {
        int cc = nf * 8 + 2 * lk;
        *(uint32_t*)(ob0 + cc) = pack_h2(oacc[nf][0] * inv0, oacc[nf][1] * inv0);
        *(uint32_t*)(ob1 + cc) = pack_h2(oacc[nf][2] * inv1, oacc[nf][3] * inv1);
    }
}

// ---------------------------------------------------------------------------
extern "C" void kernel_launch(void* const* d_in, const int* in_sizes, int n_in,
                              void* d_out, int out_size)
{
    const float* x     = (const float*)d_in[0];
    const float* w_qkv = (const float*)d_in[1];
    const float* w_out = (const float*)d_in[2];
    const float* b_out = (const float*)d_in[3];
    float* out = (float*)d_out;

    __half *qkv_p, *attn_p, *xh_p, *wqkvh_p, *wouth_p;
    cudaGetSymbolAddress((void**)&qkv_p, g_qkvh);
    cudaGetSymbolAddress((void**)&attn_p, g_attnh);
    cudaGetSymbolAddress((void**)&xh_p, g_xh);
    cudaGetSymbolAddress((void**)&wqkvh_p, g_wqkvh);
    cudaGetSymbolAddress((void**)&wouth_p, g_wouth);

    const int M = B_ * T_;

    // 0) fused fp32 -> fp16 (RTN), one launch
    convert_all_kernel<<<(N8_TOT + 255) / 256, 256>>>(
        (const float4*)x, (uint4*)xh_p,
        (const float4*)w_qkv, (uint4*)wqkvh_p,
        (const float4*)w_out, (uint4*)wouth_p);

    cudaFuncSetAttribute(gemm_mma_f16, cudaFuncAttributeMaxDynamicSharedMemorySize, G_SMEM);
    cudaFuncSetAttribute(flash_mma_f16, cudaFuncAttributeMaxDynamicSharedMemorySize, FSM_BYTES);

    // 1) qkv = x @ w_qkv^T  [8192, 3072] -> fp16
    {
        dim3 grid((3 * C_) / G_BN, M / G_BM);
        gemm_mma_f16<<<grid, 256, G_SMEM>>>(xh_p, wqkvh_p, nullptr, nullptr, qkv_p, 3 * C_);
    }

    // 2) flash attention -> g_attnh
    {
        dim3 grid(T_ / FBM, B_ * H_);
        flash_mma_f16<<<grid, 256, FSM_BYTES>>>(qkv_p, attn_p);
    }

    // 3) out = g_attn @ w_out^T + b_out  [8192, 1024] -> fp32
    {
        dim3 grid(C_ / G_BN, M / G_BM);
        gemm_mma_f16<<<grid, 256, G_SMEM>>>(attn_p, wouth_p, b_out, out, nullptr, C_);
    }
}